// round 1
// baseline (speedup 1.0000x reference)
#include <cuda_runtime.h>
#include <cuda_bf16.h>

// ---------------------------------------------------------------------------
// Problem constants (match reference exactly)
// ---------------------------------------------------------------------------
#define NXg 256
#define NBg 256
#define NK  64

static __device__ __constant__ float c_E2[8] = {
    4.0f/9.0f, 1.0f/9.0f, 1.0f/9.0f, 4.0f/9.0f,
    4.0f/9.0f, 1.0f/9.0f, 1.0f/9.0f, 4.0f/9.0f
};

// log-space grid bounds
#define LXMIN_D (-9.210340371976182)   /* log(1e-4) */
#define LBMIN_D (-6.907755278982137)   /* log(1e-3) */
#define LBMAX_D ( 3.912023005428146)   /* log(50)   */

__device__ __forceinline__ float4 lerp4(float4 a, float4 b, float t) {
    float4 r;
    r.x = fmaf(t, b.x - a.x, a.x);
    r.y = fmaf(t, b.y - a.y, a.y);
    r.z = fmaf(t, b.z - a.z, a.z);
    r.w = fmaf(t, b.w - a.w, a.w);
    return r;
}

// Transposed grids: [NX][NB][8 flavors], flavor innermost (32B per grid point).
// pdf grid has E2[f] baked in, so the flavor sum is a plain dot product.
__device__ float g_pdf_t[NXg * NBg * 8];
__device__ float g_ff_t [NXg * NBg * 8];

// ---------------------------------------------------------------------------
// Kernel 1: transpose (8,NX,NB) -> (NX*NB, 8), bake E2 into pdf.
// One thread per (i,j) grid point: 8 coalesced strided reads, 2 float4 writes.
// ---------------------------------------------------------------------------
__global__ __launch_bounds__(256)
void transpose_grids_kernel(const float* __restrict__ pdf,
                            const float* __restrict__ ff)
{
    int ij = blockIdx.x * blockDim.x + threadIdx.x;   // 0 .. NX*NB-1
    if (ij >= NXg * NBg) return;

    float pv[8], fv[8];
#pragma unroll
    for (int f = 0; f < 8; f++) {
        pv[f] = c_E2[f] * pdf[f * (NXg * NBg) + ij];
        fv[f] = ff [f * (NXg * NBg) + ij];
    }
    float4* pd = reinterpret_cast<float4*>(&g_pdf_t[ij * 8]);
    float4* fd = reinterpret_cast<float4*>(&g_ff_t [ij * 8]);
    pd[0] = make_float4(pv[0], pv[1], pv[2], pv[3]);
    pd[1] = make_float4(pv[4], pv[5], pv[6], pv[7]);
    fd[0] = make_float4(fv[0], fv[1], fv[2], fv[3]);
    fd[1] = make_float4(fv[4], fv[5], fv[6], fv[7]);
}

// ---------------------------------------------------------------------------
// Kernel 2: main — one thread per event, k-loop with exponential-cutoff break.
// ---------------------------------------------------------------------------
__global__ __launch_bounds__(256)
void sidis_kernel(const float* __restrict__ ev,      // (N,4): x, PhT, Q, z
                  const float* __restrict__ ogx,     // (64,)
                  const float* __restrict__ ogw,     // (64,)
                  const float* __restrict__ fnp,     // (4,)
                  float* __restrict__ out,
                  int n_events)
{
    __shared__ float s_u[NK], s_lu[NK], s_w[NK];
    int t = threadIdx.x;
    if (t < NK) {
        float u = ogx[t];
        s_u[t]  = u;
        s_lu[t] = __logf(u);
        s_w[t]  = ogw[t];
    }
    __syncthreads();

    int n = blockIdx.x * blockDim.x + t;
    if (n >= n_events) return;

    const float LXMIN  = (float)LXMIN_D;
    const float LBMIN  = (float)LBMIN_D;
    const float XSCALE = (float)(255.0 / (0.0 - LXMIN_D));
    const float BSCALE = (float)(255.0 / (LBMAX_D - LBMIN_D));

    float4 e = reinterpret_cast<const float4*>(ev)[n];
    float x = e.x, PhT = e.y, Q = e.z, z = e.w;

    float qT     = __fdividef(PhT, z);
    float inv_qT = __fdividef(1.0f, qT);
    float Q2     = Q * Q;

    // --- x / z grid coordinates (fixed per event) ---
    float lx = __logf(x);
    float fx = fminf(fmaxf((lx - LXMIN) * XSCALE, 0.0f), 255.0f - 1e-4f);
    int   i0p = (int)fx;
    float txp = fx - (float)i0p;

    float lz = __logf(z);
    float fz = fminf(fmaxf((lz - LXMIN) * XSCALE, 0.0f), 255.0f - 1e-4f);
    int   i0f = (int)fz;
    float txf = fz - (float)i0f;

    // --- non-perturbative params (cheap, per-thread) ---
    float p0 = fnp[0], p1 = fnp[1], p2 = fnp[2], p3 = fnp[3];
    float lam_p = log1pf(__expf(p0));                 // softplus
    float lam_f = log1pf(__expf(p1));
    float sig2  = __fdividef(1.0f, 1.0f + __expf(-p2));
    float sig3  = __fdividef(1.0f, 1.0f + __expf(-p3));

    float lQ2 = __logf(Q2);                           // Q20 = 1
    float inv_z2 = __fdividef(1.0f, z * z);
    // combined Gaussian coefficient: evo2 * f_pdf * f_ff = exp(-c * bT^2)
    float c = 0.12f * lQ2
            + lam_p * (1.0f - sig2 * lx)              // log(1/x) = -lx
            + lam_f * (1.0f + sig3) * inv_z2;

    float cq = c * inv_qT * inv_qT;                   // arg_k = -cq * u_k^2
    float log_invqT = -__logf(qT);

    float u0 = s_u[0];
    float arg_cut = fmaf(-cq, u0 * u0, -36.0f);       // arg_0 - 36

    const float* pbase = &g_pdf_t[i0p * (NBg * 8)];
    const float* fbase = &g_ff_t [i0f * (NBg * 8)];

    float acc = 0.0f;
    for (int k = 0; k < NK; k++) {
        float u   = s_u[k];
        float arg = -cq * u * u;
        if (arg < arg_cut) break;                     // all later terms negligible

        float lb = s_lu[k] + log_invqT;
        float fb = fminf(fmaxf((lb - LBMIN) * BSCALE, 0.0f), 255.0f - 1e-4f);
        int   j0 = (int)fb;
        float tb = fb - (float)j0;

        // pdf corners: rows i0p, i0p+1 ; cols j0, j0+1 ; flavor-contiguous
        const float4* pr0 = reinterpret_cast<const float4*>(pbase + j0 * 8);
        const float4* pr1 = reinterpret_cast<const float4*>(pbase + NBg * 8 + j0 * 8);
        float4 pa0 = pr0[0], pa1 = pr0[1], pb0 = pr0[2], pb1 = pr0[3];
        float4 pc0 = pr1[0], pc1 = pr1[1], pd0 = pr1[2], pd1 = pr1[3];

        const float4* fr0 = reinterpret_cast<const float4*>(fbase + j0 * 8);
        const float4* fr1 = reinterpret_cast<const float4*>(fbase + NBg * 8 + j0 * 8);
        float4 fa0 = fr0[0], fa1 = fr0[1], fb0 = fr0[2], fb1 = fr0[3];
        float4 fc0 = fr1[0], fc1 = fr1[1], fd0 = fr1[2], fd1 = fr1[3];

        // bilinear: lerp in b within each x-row, then lerp in x
        float4 pr0l = lerp4(pa0, pb0, tb);
        float4 pr0h = lerp4(pa1, pb1, tb);
        float4 pr1l = lerp4(pc0, pd0, tb);
        float4 pr1h = lerp4(pc1, pd1, tb);
        float4 pvl  = lerp4(pr0l, pr1l, txp);
        float4 pvh  = lerp4(pr0h, pr1h, txp);

        float4 fr0l = lerp4(fa0, fb0, tb);
        float4 fr0h = lerp4(fa1, fb1, tb);
        float4 fr1l = lerp4(fc0, fd0, tb);
        float4 fr1h = lerp4(fc1, fd1, tb);
        float4 fvl  = lerp4(fr0l, fr1l, txf);
        float4 fvh  = lerp4(fr0h, fr1h, txf);

        float s = pvl.x * fvl.x + pvl.y * fvl.y + pvl.z * fvl.z + pvl.w * fvl.w
                + pvh.x * fvh.x + pvh.y * fvh.y + pvh.z * fvh.z + pvh.w * fvh.w;

        acc = fmaf(s * s_w[k], __expf(arg), acc);
    }

    float FUUT = acc * inv_qT * inv_qT;

    // --- prefactor ---
    const float ALPHA0 = 0.00729735253f;              // 1/137.035999
    const float L_ME2  = 15.1582899f;                 // -log(0.000511^2)
    float lQme = lQ2 + L_ME2;                         // log(Q2/ME2)
    float alpha = __fdividef(ALPHA0, 1.0f - (ALPHA0 / (3.0f * 3.14159265358979f)) * lQme);
    float gamma = 2.0f * 0.8803f * x / Q;
    float y  = __fdividef(Q2, x * (140.0f - 0.8803f));
    float g2y2 = gamma * gamma * y * y;
    float epsn = 1.0f - y - 0.25f * g2y2;
    float epsd = 1.0f - y + 0.5f * y * y + 0.25f * g2y2;
    float eps  = __fdividef(epsn, epsd);
    float pre = 78.9568352f                            // 8*pi^2
              * alpha * alpha * (z * z) * qT
              * __fdividef(1.0f, x * Q2 * Q)
              * (y * y) * 0.5f * __fdividef(1.0f, 1.0f - eps)
              * (1.0f + gamma * gamma / (2.0f * x));

    out[n] = pre * FUUT;
}

// ---------------------------------------------------------------------------
// kernel_launch
// Inputs (metadata order): events_tensor (N,4), ope_pdf_grid (8,256,256),
// ope_ff_grid (8,256,256), ogata_x (64,), ogata_w (64,), fnp_params (4,)
// ---------------------------------------------------------------------------
extern "C" void kernel_launch(void* const* d_in, const int* in_sizes, int n_in,
                              void* d_out, int out_size)
{
    const float* ev   = (const float*)d_in[0];
    const float* pdfg = (const float*)d_in[1];
    const float* ffg  = (const float*)d_in[2];
    const float* ogx  = (const float*)d_in[3];
    const float* ogw  = (const float*)d_in[4];
    const float* fnp  = (const float*)d_in[5];
    float* out = (float*)d_out;

    int n_events = in_sizes[0] / 4;

    transpose_grids_kernel<<<(NXg * NBg + 255) / 256, 256>>>(pdfg, ffg);

    int blocks = (n_events + 255) / 256;
    sidis_kernel<<<blocks, 256>>>(ev, ogx, ogw, fnp, out, n_events);
}